// round 13
// baseline (speedup 1.0000x reference)
#include <cuda_runtime.h>
#include <cuda_bf16.h>
#include <cstdint>

#define BQ   64
#define SEQ  341
#define DIM  768
#define NH   12
#define HD   64
#define MROWS (BQ * SEQ)      // 21824
#define QKV_COLS (3 * DIM)    // 2304
#define ROWTILES 171          // ceil(21824/128)
#define KTILES   24           // 768/32
#define ROWT2    86           // ceil(ROWTILES/2): 256-row block tiles

// Scratch (no device allocation allowed). __device__ globals are zero-init.
__device__ float g_q[(size_t)BQ * NH * SEQ * HD];
__device__ float g_k[(size_t)BQ * NH * SEQ * HD];
__device__ float g_v[(size_t)BQ * NH * SEQ * HD];

// Pre-formatted tf32-bit tiled buffers: [tile][kTile][r=128][permuted c=32]
__device__ uint32_t g_xt[(size_t)ROWTILES * KTILES * 4096];
__device__ uint32_t g_aot[(size_t)ROWTILES * KTILES * 4096];
__device__ uint32_t g_wq[(size_t)(QKV_COLS / 128) * KTILES * 4096];
__device__ uint32_t g_wp[(size_t)(DIM / 128) * KTILES * 4096];

// ---------------------------------------------------------------------------
// Helpers
// ---------------------------------------------------------------------------

__device__ __forceinline__ uint32_t to_tf32(float x) {
    uint32_t y;
    asm("cvt.rna.tf32.f32 %0, %1;" : "=r"(y) : "f"(x));
    return y;
}

__device__ __forceinline__ void mma_tf32(float& c0, float& c1, float& c2, float& c3,
                                         uint32_t a0, uint32_t a1, uint32_t a2, uint32_t a3,
                                         uint32_t b0, uint32_t b1) {
    asm volatile(
        "mma.sync.aligned.m16n8k8.row.col.f32.tf32.tf32.f32 "
        "{%0,%1,%2,%3}, {%4,%5,%6,%7}, {%8,%9}, {%0,%1,%2,%3};\n"
        : "+f"(c0), "+f"(c1), "+f"(c2), "+f"(c3)
        : "r"(a0), "r"(a1), "r"(a2), "r"(a3), "r"(b0), "r"(b1));
}

#define CP_ASYNC16(dst32, src) \
    asm volatile("cp.async.cg.shared.global [%0], [%1], 16;\n" :: "r"(dst32), "l"(src))
#define CP_COMMIT()  asm volatile("cp.async.commit_group;\n" ::: "memory")
#define CP_WAIT0()   asm volatile("cp.async.wait_group 0;\n" ::: "memory")

// ---------------------------------------------------------------------------
// Format pass: fp32 row-major [nrows x 768] -> tiled permuted tf32 bits.
// word(tile,kt,r,c) = ((tile*24+kt)*128 + r)*32 + (c&3)*8 + (c>>2)
// ---------------------------------------------------------------------------

__global__ __launch_bounds__(192) void fmt_kernel(
    const float* __restrict__ src, uint32_t* __restrict__ dst)
{
    const int m = blockIdx.x;
    const int f = threadIdx.x;          // float4 index 0..191
    const float4 v = *reinterpret_cast<const float4*>(src + (size_t)m * DIM + f * 4);
    const int rowTile = m >> 7;
    const int r = m & 127;
    const int kt = f >> 3;
    const int f4 = f & 7;
    uint32_t* p = dst + ((size_t)(rowTile * KTILES + kt) * 128 + r) * 32 + f4;
    p[0]  = to_tf32(v.x);
    p[8]  = to_tf32(v.y);
    p[16] = to_tf32(v.z);
    p[24] = to_tf32(v.w);
}

// ---------------------------------------------------------------------------
// TF32 GEMM on pre-formatted tiles. C[m,n] = sum_k A[m,k]*W[n,k] (+bias).
// Block tile 256x128, BK=32, 256 thr = 8 warps (4x2), warp tile 64x64.
// cp.async double-buffered. mode 0: scatter q/k/v. mode 1: out[m][e].
// blockIdx.x = colTile (fast), blockIdx.y = 256-row tile.
// ---------------------------------------------------------------------------

__global__ __launch_bounds__(256, 1) void gemm_fmt_kernel(
    const uint32_t* __restrict__ At, const uint32_t* __restrict__ Wt,
    const float* __restrict__ bias, float* __restrict__ out, int mode)
{
    extern __shared__ uint32_t sh[];
    uint32_t* sA = sh;            // [2][8192]  (256 rows x 32)
    uint32_t* sB = sh + 16384;    // [2][4096]  (128 rows x 32)

    const int tid  = threadIdx.x;
    const int warp = tid >> 5;
    const int lane = tid & 31;
    const int warp_m = warp >> 1;   // 0..3 -> rows warp_m*64
    const int warp_n = warp & 1;    // 0..1 -> cols warp_n*64
    const int grp  = lane >> 2;     // 0..7
    const int thr  = lane & 3;      // 0..3
    const int colT = blockIdx.x;
    const int rowT = blockIdx.y;

    const int rt0 = rowT * 2;
    const int rt1 = (rt0 + 1 < ROWTILES) ? rt0 + 1 : rt0;  // dummy for last block
    const uint32_t* gA0 = At + (size_t)rt0 * KTILES * 4096;
    const uint32_t* gA1 = At + (size_t)rt1 * KTILES * 4096;
    const uint32_t* gB  = Wt + (size_t)colT * KTILES * 4096;

    float acc[4][8][4];
    #pragma unroll
    for (int i = 0; i < 4; i++)
        #pragma unroll
        for (int j = 0; j < 8; j++)
            #pragma unroll
            for (int c = 0; c < 4; c++) acc[i][j][c] = 0.f;

    // prefetch kt=0 into buffer 0
    {
        uint32_t dA = (uint32_t)__cvta_generic_to_shared(sA);
        uint32_t dB = (uint32_t)__cvta_generic_to_shared(sB);
        #pragma unroll
        for (int i = 0; i < 4; i++) {
            int off = (i * 256 + tid) * 4;
            CP_ASYNC16(dA + off * 4, gA0 + off);                 // rows 0..127
            CP_ASYNC16(dA + (off + 4096) * 4, gA1 + off);        // rows 128..255
            CP_ASYNC16(dB + off * 4, gB + off);
        }
        CP_COMMIT();
    }

    for (int kt = 0; kt < KTILES; kt++) {
        const int cur = kt & 1;
        CP_WAIT0();
        __syncthreads();

        if (kt + 1 < KTILES) {
            const int nxt = cur ^ 1;
            uint32_t dA = (uint32_t)__cvta_generic_to_shared(sA + nxt * 8192);
            uint32_t dB = (uint32_t)__cvta_generic_to_shared(sB + nxt * 4096);
            const uint32_t* srcA0 = gA0 + (size_t)(kt + 1) * 4096;
            const uint32_t* srcA1 = gA1 + (size_t)(kt + 1) * 4096;
            const uint32_t* srcB  = gB  + (size_t)(kt + 1) * 4096;
            #pragma unroll
            for (int i = 0; i < 4; i++) {
                int off = (i * 256 + tid) * 4;
                CP_ASYNC16(dA + off * 4, srcA0 + off);
                CP_ASYNC16(dA + (off + 4096) * 4, srcA1 + off);
                CP_ASYNC16(dB + off * 4, srcB + off);
            }
            CP_COMMIT();
        }

        const uint32_t* A0 = sA + cur * 8192;
        const uint32_t* B0 = sB + cur * 4096;

        #pragma unroll
        for (int half = 0; half < 2; half++) {
            uint4 va[4][2];
            #pragma unroll
            for (int ms = 0; ms < 4; ms++) {
                int r0 = warp_m * 64 + ms * 16 + grp;
                va[ms][0] = *reinterpret_cast<const uint4*>(&A0[r0 * 32 + thr * 8 + half * 4]);
                va[ms][1] = *reinterpret_cast<const uint4*>(&A0[(r0 + 8) * 32 + thr * 8 + half * 4]);
            }
            #pragma unroll
            for (int ns = 0; ns < 8; ns++) {
                int rn = warp_n * 64 + ns * 8 + grp;
                uint4 vb = *reinterpret_cast<const uint4*>(&B0[rn * 32 + thr * 8 + half * 4]);
                #pragma unroll
                for (int ms = 0; ms < 4; ms++) {
                    mma_tf32(acc[ms][ns][0], acc[ms][ns][1], acc[ms][ns][2], acc[ms][ns][3],
                             va[ms][0].x, va[ms][1].x, va[ms][0].y, va[ms][1].y,
                             vb.x, vb.y);
                    mma_tf32(acc[ms][ns][0], acc[ms][ns][1], acc[ms][ns][2], acc[ms][ns][3],
                             va[ms][0].z, va[ms][1].z, va[ms][0].w, va[ms][1].w,
                             vb.z, vb.w);
                }
            }
        }
        __syncthreads();
    }

    // Epilogue
    #pragma unroll
    for (int ms = 0; ms < 4; ms++) {
        #pragma unroll
        for (int ns = 0; ns < 8; ns++) {
            #pragma unroll
            for (int c = 0; c < 4; c++) {
                int m = rowT * 256 + warp_m * 64 + ms * 16 + grp + ((c >= 2) ? 8 : 0);
                if (m >= MROWS) continue;
                int e = colT * 128 + warp_n * 64 + ns * 8 + thr * 2 + (c & 1);
                float val = acc[ms][ns][c] + __ldg(&bias[e]);
                if (mode == 0) {
                    int b = m / SEQ;
                    int n = m - b * SEQ;
                    int which = e / DIM;
                    int d = e - which * DIM;
                    int h = d >> 6;
                    int hh = d & 63;
                    float* dst = (which == 0) ? g_q : (which == 1) ? g_k : g_v;
                    dst[(((size_t)b * NH + h) * SEQ + n) * HD + hh] = val;
                } else {
                    out[(size_t)m * DIM + e] = val;
                }
            }
        }
    }
}

// ---------------------------------------------------------------------------
// Tensor-core flash attention (validated R10/R12 version). Writes g_aot tiled.
// ---------------------------------------------------------------------------

#define AS 68    // row stride (64 + 4)
#define KT 64    // key tile
#define NEGINF (-1e30f)

__device__ __forceinline__ int kmax_for_row(int r) {
    if (r == 0)  return SEQ;
    if (r < 5)   return 5;
    if (r < 21)  return 21;
    if (r < 85)  return 85;
    return SEQ;
}

__global__ __launch_bounds__(256) void attn_mma_kernel() {
    extern __shared__ uint32_t sm[];
    uint32_t* Qs = sm;                 // [128][AS]
    uint32_t* Ks = Qs + 128 * AS;      // [64][AS]
    uint32_t* Vs = Ks + KT * AS;       // [64][AS]
    uint32_t* Ps = Vs + KT * AS;       // [128][AS]

    const int tid  = threadIdx.x;
    const int warp = tid >> 5;
    const int lane = tid & 31;
    const int grp  = lane >> 2;
    const int thr  = lane & 3;
    const int bh   = blockIdx.x;
    const int qt   = blockIdx.y;
    const size_t base = (size_t)bh * SEQ * HD;
    const int b = bh / NH;
    const int h = bh - b * NH;
    const int w16 = warp * 16;

    for (int idx = tid; idx < 128 * 16; idx += 256) {
        int r  = idx >> 4;
        int c4 = (idx & 15) << 2;
        int qrow = qt * 128 + r;
        float4 v = (qrow < SEQ)
            ? *reinterpret_cast<const float4*>(g_q + base + (size_t)qrow * HD + c4)
            : make_float4(0.f, 0.f, 0.f, 0.f);
        uint32_t* p = &Qs[r * AS + c4];
        p[0] = to_tf32(v.x); p[1] = to_tf32(v.y);
        p[2] = to_tf32(v.z); p[3] = to_tf32(v.w);
    }

    const int gr0 = qt * 128 + w16 + grp;
    const int gr1 = gr0 + 8;
    const int km0 = kmax_for_row(gr0);
    const int km1 = kmax_for_row(gr1);
    const int wkm = (qt == 0 && warp == 0) ? SEQ : kmax_for_row(qt * 128 + w16 + 15);

    float m0 = NEGINF, m1 = NEGINF, l0 = 0.f, l1 = 0.f;
    float oacc[8][4];
    #pragma unroll
    for (int no = 0; no < 8; no++)
        #pragma unroll
        for (int c = 0; c < 4; c++) oacc[no][c] = 0.f;

    for (int t = 0; t < 6; t++) {
        __syncthreads();

        for (int idx = tid; idx < KT * 16; idx += 256) {
            int r  = idx >> 4;
            int c4 = (idx & 15) << 2;
            int krow = t * KT + r;
            float4 kv, vv;
            if (krow < SEQ) {
                kv = *reinterpret_cast<const float4*>(g_k + base + (size_t)krow * HD + c4);
                vv = *reinterpret_cast<const float4*>(g_v + base + (size_t)krow * HD + c4);
            } else {
                kv = make_float4(0.f, 0.f, 0.f, 0.f);
                vv = kv;
            }
            uint32_t* pk = &Ks[r * AS + c4];
            pk[0] = to_tf32(kv.x); pk[1] = to_tf32(kv.y);
            pk[2] = to_tf32(kv.z); pk[3] = to_tf32(kv.w);
            uint32_t* pv = &Vs[r * AS + c4];
            pv[0] = to_tf32(vv.x); pv[1] = to_tf32(vv.y);
            pv[2] = to_tf32(vv.z); pv[3] = to_tf32(vv.w);
        }
        __syncthreads();

        if (t * KT >= wkm) continue;

        float sacc[8][4];
        #pragma unroll
        for (int ns = 0; ns < 8; ns++)
            #pragma unroll
            for (int c = 0; c < 4; c++) sacc[ns][c] = 0.f;

        #pragma unroll
        for (int kk = 0; kk < 64; kk += 8) {
            uint32_t a0 = Qs[(w16 + grp)     * AS + kk + thr];
            uint32_t a1 = Qs[(w16 + grp + 8) * AS + kk + thr];
            uint32_t a2 = Qs[(w16 + grp)     * AS + kk + thr + 4];
            uint32_t a3 = Qs[(w16 + grp + 8) * AS + kk + thr + 4];
            #pragma unroll
            for (int ns = 0; ns < 8; ns++) {
                uint32_t b0 = Ks[(ns * 8 + grp) * AS + kk + thr];
                uint32_t b1 = Ks[(ns * 8 + grp) * AS + kk + thr + 4];
                mma_tf32(sacc[ns][0], sacc[ns][1], sacc[ns][2], sacc[ns][3],
                         a0, a1, a2, a3, b0, b1);
            }
        }

        float tmax0 = NEGINF, tmax1 = NEGINF;
        #pragma unroll
        for (int ns = 0; ns < 8; ns++) {
            int j0 = t * KT + ns * 8 + thr * 2;
            sacc[ns][0] = (j0     < km0) ? sacc[ns][0] * 0.125f : NEGINF;
            sacc[ns][1] = (j0 + 1 < km0) ? sacc[ns][1] * 0.125f : NEGINF;
            sacc[ns][2] = (j0     < km1) ? sacc[ns][2] * 0.125f : NEGINF;
            sacc[ns][3] = (j0 + 1 < km1) ? sacc[ns][3] * 0.125f : NEGINF;
            tmax0 = fmaxf(tmax0, fmaxf(sacc[ns][0], sacc[ns][1]));
            tmax1 = fmaxf(tmax1, fmaxf(sacc[ns][2], sacc[ns][3]));
        }
        tmax0 = fmaxf(tmax0, __shfl_xor_sync(0xFFFFFFFFu, tmax0, 1));
        tmax0 = fmaxf(tmax0, __shfl_xor_sync(0xFFFFFFFFu, tmax0, 2));
        tmax1 = fmaxf(tmax1, __shfl_xor_sync(0xFFFFFFFFu, tmax1, 1));
        tmax1 = fmaxf(tmax1, __shfl_xor_sync(0xFFFFFFFFu, tmax1, 2));

        float mn0 = fmaxf(m0, tmax0);
        float mn1 = fmaxf(m1, tmax1);
        float cr0 = __expf(m0 - mn0);
        float cr1 = __expf(m1 - mn1);
        m0 = mn0; m1 = mn1;

        float rs0 = 0.f, rs1 = 0.f;
        #pragma unroll
        for (int ns = 0; ns < 8; ns++) {
            sacc[ns][0] = __expf(sacc[ns][0] - mn0);
            sacc[ns][1] = __expf(sacc[ns][1] - mn0);
            sacc[ns][2] = __expf(sacc[ns][2] - mn1);
            sacc[ns][3] = __expf(sacc[ns][3] - mn1);
            rs0 += sacc[ns][0] + sacc[ns][1];
            rs1 += sacc[ns][2] + sacc[ns][3];
        }
        rs0 += __shfl_xor_sync(0xFFFFFFFFu, rs0, 1);
        rs0 += __shfl_xor_sync(0xFFFFFFFFu, rs0, 2);
        rs1 += __shfl_xor_sync(0xFFFFFFFFu, rs1, 1);
        rs1 += __shfl_xor_sync(0xFFFFFFFFu, rs1, 2);
        l0 = l0 * cr0 + rs0;
        l1 = l1 * cr1 + rs1;

        #pragma unroll
        for (int no = 0; no < 8; no++) {
            oacc[no][0] *= cr0; oacc[no][1] *= cr0;
            oacc[no][2] *= cr1; oacc[no][3] *= cr1;
        }

        #pragma unroll
        for (int ns = 0; ns < 8; ns++) {
            int col = ns * 8 + thr * 2;
            Ps[(w16 + grp)     * AS + col]     = to_tf32(sacc[ns][0]);
            Ps[(w16 + grp)     * AS + col + 1] = to_tf32(sacc[ns][1]);
            Ps[(w16 + grp + 8) * AS + col]     = to_tf32(sacc[ns][2]);
            Ps[(w16 + grp + 8) * AS + col + 1] = to_tf32(sacc[ns][3]);
        }
        __syncwarp();

        #pragma unroll
        for (int kk = 0; kk < 64; kk += 8) {
            uint32_t a0 = Ps[(w16 + grp)     * AS + kk + thr];
            uint32_t a1 = Ps[(w16 + grp + 8) * AS + kk + thr];
            uint32_t a2 = Ps[(w16 + grp)     * AS + kk + thr + 4];
            uint32_t a3 = Ps[(w16 + grp + 8) * AS + kk + thr + 4];
            #pragma unroll
            for (int no = 0; no < 8; no++) {
                uint32_t b0 = Vs[(kk + thr)     * AS + no * 8 + grp];
                uint32_t b1 = Vs[(kk + thr + 4) * AS + no * 8 + grp];
                mma_tf32(oacc[no][0], oacc[no][1], oacc[no][2], oacc[no][3],
                         a0, a1, a2, a3, b0, b1);
            }
        }
    }

    // Normalize, write directly into tiled tf32 buffer g_aot.
    float inv0 = 1.f / l0;
    float inv1 = 1.f / l1;
    #pragma unroll
    for (int no = 0; no < 8; no++) {
        int d = no * 8 + thr * 2;
        int e = h * HD + d;
        int ktile = e >> 5;
        int c = e & 31;
        uint32_t coff = (uint32_t)((c & 3) * 8 + (c >> 2));
        if (gr0 < SEQ) {
            int mg = b * SEQ + gr0;
            uint32_t* p = g_aot + ((size_t)((mg >> 7) * KTILES + ktile) * 128 + (mg & 127)) * 32 + coff;
            p[0] = to_tf32(oacc[no][0] * inv0);
            p[8] = to_tf32(oacc[no][1] * inv0);
        }
        if (gr1 < SEQ) {
            int mg = b * SEQ + gr1;
            uint32_t* p = g_aot + ((size_t)((mg >> 7) * KTILES + ktile) * 128 + (mg & 127)) * 32 + coff;
            p[0] = to_tf32(oacc[no][2] * inv1);
            p[8] = to_tf32(oacc[no][3] * inv1);
        }
    }
}

// ---------------------------------------------------------------------------

extern "C" void kernel_launch(void* const* d_in, const int* in_sizes, int n_in,
                              void* d_out, int out_size) {
    const float* x      = (const float*)d_in[0];
    const float* qkv_w  = (const float*)d_in[1];
    const float* qkv_b  = (const float*)d_in[2];
    const float* proj_w = (const float*)d_in[3];
    const float* proj_b = (const float*)d_in[4];
    float* out = (float*)d_out;

    uint32_t* xt;  cudaGetSymbolAddress((void**)&xt,  g_xt);
    uint32_t* aot; cudaGetSymbolAddress((void**)&aot, g_aot);
    uint32_t* wq;  cudaGetSymbolAddress((void**)&wq,  g_wq);
    uint32_t* wp;  cudaGetSymbolAddress((void**)&wp,  g_wp);

    const int smem_gemm = (2 * 8192 + 2 * 4096) * (int)sizeof(uint32_t);  // 98304
    const int smem_attn = (128 * AS + KT * AS + KT * AS + 128 * AS) * (int)sizeof(uint32_t);
    cudaFuncSetAttribute(gemm_fmt_kernel, cudaFuncAttributeMaxDynamicSharedMemorySize, smem_gemm);
    cudaFuncSetAttribute(attn_mma_kernel, cudaFuncAttributeMaxDynamicSharedMemorySize, smem_attn);

    // Format passes
    fmt_kernel<<<MROWS, 192>>>(x, xt);
    fmt_kernel<<<QKV_COLS, 192>>>(qkv_w, wq);
    fmt_kernel<<<DIM, 192>>>(proj_w, wp);

    // QKV GEMM (256-row tiles)
    dim3 gQkv(QKV_COLS / 128, ROWT2);      // 18 x 86
    gemm_fmt_kernel<<<gQkv, 256, smem_gemm>>>(xt, wq, qkv_b, nullptr, 0);

    // Attention (writes g_aot tiled)
    dim3 gAttn(BQ * NH, 3);                // 768 x 3
    attn_mma_kernel<<<gAttn, 256, smem_attn>>>();

    // Proj GEMM
    dim3 gProj(DIM / 128, ROWT2);          // 6 x 86
    gemm_fmt_kernel<<<gProj, 256, smem_gemm>>>(aot, wp, proj_b, out, 1);
}

// round 14
// speedup vs baseline: 1.2079x; 1.2079x over previous
#include <cuda_runtime.h>
#include <cuda_bf16.h>
#include <cstdint>

#define BQ   64
#define SEQ  341
#define DIM  768
#define NH   12
#define HD   64
#define MROWS (BQ * SEQ)      // 21824
#define QKV_COLS (3 * DIM)    // 2304
#define ROWTILES 171          // ceil(21824/128)
#define KTILES   24           // 768/32
#define PADROWS  64           // zero padding rows for OOB tile reads

// Scratch (no device allocation allowed). __device__ globals are zero-init;
// padding rows are never written so they stay zero across graph replays.
// q/k/v hold tf32 BIT PATTERNS (written pre-converted by the qkv epilogue).
__device__ uint32_t g_q[((size_t)BQ * NH * SEQ + PADROWS) * HD];
__device__ uint32_t g_k[((size_t)BQ * NH * SEQ + PADROWS) * HD];
__device__ uint32_t g_v[((size_t)BQ * NH * SEQ + PADROWS) * HD];

// Pre-formatted tf32-bit tiled buffers: [tile][kTile][r=128][permuted c=32]
__device__ uint32_t g_xt[(size_t)ROWTILES * KTILES * 4096];
__device__ uint32_t g_aot[(size_t)ROWTILES * KTILES * 4096];
__device__ uint32_t g_wq[(size_t)(QKV_COLS / 128) * KTILES * 4096];
__device__ uint32_t g_wp[(size_t)(DIM / 128) * KTILES * 4096];

// ---------------------------------------------------------------------------
// Helpers
// ---------------------------------------------------------------------------

__device__ __forceinline__ uint32_t to_tf32(float x) {
    uint32_t y;
    asm("cvt.rna.tf32.f32 %0, %1;" : "=r"(y) : "f"(x));
    return y;
}

__device__ __forceinline__ void mma_tf32(float& c0, float& c1, float& c2, float& c3,
                                         uint32_t a0, uint32_t a1, uint32_t a2, uint32_t a3,
                                         uint32_t b0, uint32_t b1) {
    asm volatile(
        "mma.sync.aligned.m16n8k8.row.col.f32.tf32.tf32.f32 "
        "{%0,%1,%2,%3}, {%4,%5,%6,%7}, {%8,%9}, {%0,%1,%2,%3};\n"
        : "+f"(c0), "+f"(c1), "+f"(c2), "+f"(c3)
        : "r"(a0), "r"(a1), "r"(a2), "r"(a3), "r"(b0), "r"(b1));
}

#define CP_ASYNC16(dst32, src) \
    asm volatile("cp.async.cg.shared.global [%0], [%1], 16;\n" :: "r"(dst32), "l"(src))
#define CP_COMMIT()  asm volatile("cp.async.commit_group;\n" ::: "memory")
#define CP_WAIT0()   asm volatile("cp.async.wait_group 0;\n" ::: "memory")

// ---------------------------------------------------------------------------
// Format pass: fp32 row-major [nrows x 768] -> tiled permuted tf32 bits.
// word(tile,kt,r,c) = ((tile*24+kt)*128 + r)*32 + (c&3)*8 + (c>>2)
// ---------------------------------------------------------------------------

__global__ __launch_bounds__(192) void fmt_kernel(
    const float* __restrict__ src, uint32_t* __restrict__ dst)
{
    const int m = blockIdx.x;
    const int f = threadIdx.x;          // float4 index 0..191
    const float4 v = *reinterpret_cast<const float4*>(src + (size_t)m * DIM + f * 4);
    const int rowTile = m >> 7;
    const int r = m & 127;
    const int kt = f >> 3;
    const int f4 = f & 7;
    uint32_t* p = dst + ((size_t)(rowTile * KTILES + kt) * 128 + r) * 32 + f4;
    p[0]  = to_tf32(v.x);
    p[8]  = to_tf32(v.y);
    p[16] = to_tf32(v.z);
    p[24] = to_tf32(v.w);
}

// ---------------------------------------------------------------------------
// TF32 GEMM on pre-formatted tiles (R12 geometry: 128x128, BK=32, 8 warps 4x2,
// cp.async double-buffered). mode 0: scatter tf32 bits to g_q/g_k/g_v.
// mode 1: out[m][e] = val (fp32).
// ---------------------------------------------------------------------------

__global__ __launch_bounds__(256) void gemm_fmt_kernel(
    const uint32_t* __restrict__ At, const uint32_t* __restrict__ Wt,
    const float* __restrict__ bias, float* __restrict__ out, int mode)
{
    extern __shared__ uint32_t sh[];
    uint32_t* sA = sh;           // [2][4096]
    uint32_t* sB = sh + 8192;    // [2][4096]

    const int tid  = threadIdx.x;
    const int warp = tid >> 5;
    const int lane = tid & 31;
    const int warp_m = warp >> 1;
    const int warp_n = warp & 1;
    const int grp  = lane >> 2;
    const int thr  = lane & 3;
    const int colT = blockIdx.x;
    const int rowT = blockIdx.y;

    const uint32_t* gA = At + (size_t)rowT * KTILES * 4096;
    const uint32_t* gB = Wt + (size_t)colT * KTILES * 4096;

    float acc[2][8][4];
    #pragma unroll
    for (int i = 0; i < 2; i++)
        #pragma unroll
        for (int j = 0; j < 8; j++)
            #pragma unroll
            for (int c = 0; c < 4; c++) acc[i][j][c] = 0.f;

    {
        uint32_t dA = (uint32_t)__cvta_generic_to_shared(sA);
        uint32_t dB = (uint32_t)__cvta_generic_to_shared(sB);
        #pragma unroll
        for (int i = 0; i < 4; i++) {
            int off = (i * 256 + tid) * 4;
            CP_ASYNC16(dA + off * 4, gA + off);
            CP_ASYNC16(dB + off * 4, gB + off);
        }
        CP_COMMIT();
    }

    for (int kt = 0; kt < KTILES; kt++) {
        const int cur = kt & 1;
        CP_WAIT0();
        __syncthreads();

        if (kt + 1 < KTILES) {
            const int nxt = cur ^ 1;
            uint32_t dA = (uint32_t)__cvta_generic_to_shared(sA + nxt * 4096);
            uint32_t dB = (uint32_t)__cvta_generic_to_shared(sB + nxt * 4096);
            const uint32_t* srcA = gA + (size_t)(kt + 1) * 4096;
            const uint32_t* srcB = gB + (size_t)(kt + 1) * 4096;
            #pragma unroll
            for (int i = 0; i < 4; i++) {
                int off = (i * 256 + tid) * 4;
                CP_ASYNC16(dA + off * 4, srcA + off);
                CP_ASYNC16(dB + off * 4, srcB + off);
            }
            CP_COMMIT();
        }

        const uint32_t* A0 = sA + cur * 4096;
        const uint32_t* B0 = sB + cur * 4096;

        #pragma unroll
        for (int half = 0; half < 2; half++) {
            uint4 va[2][2];
            #pragma unroll
            for (int ms = 0; ms < 2; ms++) {
                int r0 = warp_m * 32 + ms * 16 + grp;
                va[ms][0] = *reinterpret_cast<const uint4*>(&A0[r0 * 32 + thr * 8 + half * 4]);
                va[ms][1] = *reinterpret_cast<const uint4*>(&A0[(r0 + 8) * 32 + thr * 8 + half * 4]);
            }
            #pragma unroll
            for (int ns = 0; ns < 8; ns++) {
                int rn = warp_n * 64 + ns * 8 + grp;
                uint4 vb = *reinterpret_cast<const uint4*>(&B0[rn * 32 + thr * 8 + half * 4]);
                #pragma unroll
                for (int ms = 0; ms < 2; ms++) {
                    mma_tf32(acc[ms][ns][0], acc[ms][ns][1], acc[ms][ns][2], acc[ms][ns][3],
                             va[ms][0].x, va[ms][1].x, va[ms][0].y, va[ms][1].y,
                             vb.x, vb.y);
                    mma_tf32(acc[ms][ns][0], acc[ms][ns][1], acc[ms][ns][2], acc[ms][ns][3],
                             va[ms][0].z, va[ms][1].z, va[ms][0].w, va[ms][1].w,
                             vb.z, vb.w);
                }
            }
        }
        __syncthreads();
    }

    // Epilogue
    #pragma unroll
    for (int ms = 0; ms < 2; ms++) {
        #pragma unroll
        for (int ns = 0; ns < 8; ns++) {
            #pragma unroll
            for (int c = 0; c < 4; c++) {
                int m = rowT * 128 + warp_m * 32 + ms * 16 + grp + ((c >= 2) ? 8 : 0);
                if (m >= MROWS) continue;
                int e = colT * 128 + warp_n * 64 + ns * 8 + thr * 2 + (c & 1);
                float val = acc[ms][ns][c] + __ldg(&bias[e]);
                if (mode == 0) {
                    int b = m / SEQ;
                    int n = m - b * SEQ;
                    int which = e / DIM;
                    int d = e - which * DIM;
                    int h = d >> 6;
                    int hh = d & 63;
                    uint32_t* dst = (which == 0) ? g_q : (which == 1) ? g_k : g_v;
                    dst[(((size_t)b * NH + h) * SEQ + n) * HD + hh] = to_tf32(val);
                } else {
                    out[(size_t)m * DIM + e] = val;
                }
            }
        }
    }
}

// ---------------------------------------------------------------------------
// Tensor-core flash attention, K-tile 64, cp.async staging of pre-converted
// tf32 bits (no cvt, no register round-trip). 104 KB smem -> 2 CTAs/SM.
// ---------------------------------------------------------------------------

#define AS 68    // row stride (64 + 4)
#define KT 64    // key tile
#define NEGINF (-1e30f)

__device__ __forceinline__ int kmax_for_row(int r) {
    if (r == 0)  return SEQ;   // CLS attends everywhere
    if (r < 5)   return 5;
    if (r < 21)  return 21;
    if (r < 85)  return 85;
    return SEQ;
}

__global__ __launch_bounds__(256) void attn_mma_kernel() {
    extern __shared__ uint32_t sm[];
    uint32_t* Qs = sm;                 // [128][AS]
    uint32_t* Ks = Qs + 128 * AS;      // [64][AS]
    uint32_t* Vs = Ks + KT * AS;       // [64][AS]
    uint32_t* Ps = Vs + KT * AS;       // [128][AS]

    const int tid  = threadIdx.x;
    const int warp = tid >> 5;
    const int lane = tid & 31;
    const int grp  = lane >> 2;
    const int thr  = lane & 3;
    const int bh   = blockIdx.x;
    const int qt   = blockIdx.y;
    const size_t base = (size_t)bh * SEQ * HD;
    const int b = bh / NH;
    const int h = bh - b * NH;
    const int w16 = warp * 16;

    const uint32_t qsA = (uint32_t)__cvta_generic_to_shared(Qs);
    const uint32_t ksA = (uint32_t)__cvta_generic_to_shared(Ks);
    const uint32_t vsA = (uint32_t)__cvta_generic_to_shared(Vs);

    // Stage Q tile [128 x 64] via cp.async (tf32 bits; padded rows read zeros)
    #pragma unroll
    for (int i = 0; i < 8; i++) {
        int idx = i * 256 + tid;        // 0..2047
        int r   = idx >> 4;             // 0..127
        int c4  = (idx & 15) * 4;
        CP_ASYNC16(qsA + (r * AS + c4) * 4,
                   g_q + base + (size_t)(qt * 128 + r) * HD + c4);
    }
    CP_COMMIT();

    const int gr0 = qt * 128 + w16 + grp;
    const int gr1 = gr0 + 8;
    const int km0 = kmax_for_row(gr0);
    const int km1 = kmax_for_row(gr1);
    const int wkm = (qt == 0 && warp == 0) ? SEQ : kmax_for_row(qt * 128 + w16 + 15);

    float m0 = NEGINF, m1 = NEGINF, l0 = 0.f, l1 = 0.f;
    float oacc[8][4];
    #pragma unroll
    for (int no = 0; no < 8; no++)
        #pragma unroll
        for (int c = 0; c < 4; c++) oacc[no][c] = 0.f;

    for (int t = 0; t < 6; t++) {
        __syncthreads();   // prior tile's smem reads done

        // Stage K and V tiles [64 x 64] via cp.async
        #pragma unroll
        for (int i = 0; i < 4; i++) {
            int idx = i * 256 + tid;    // 0..1023
            int r   = idx >> 4;         // 0..63
            int c4  = (idx & 15) * 4;
            size_t goff = base + (size_t)(t * KT + r) * HD + c4;
            CP_ASYNC16(ksA + (r * AS + c4) * 4, g_k + goff);
            CP_ASYNC16(vsA + (r * AS + c4) * 4, g_v + goff);
        }
        CP_COMMIT();
        CP_WAIT0();        // Q (t=0) + this tile's K/V complete
        __syncthreads();

        if (t * KT >= wkm) continue;

        // S = Q K^T : 16 q-rows x 64 keys
        float sacc[8][4];
        #pragma unroll
        for (int ns = 0; ns < 8; ns++)
            #pragma unroll
            for (int c = 0; c < 4; c++) sacc[ns][c] = 0.f;

        #pragma unroll
        for (int kk = 0; kk < 64; kk += 8) {
            uint32_t a0 = Qs[(w16 + grp)     * AS + kk + thr];
            uint32_t a1 = Qs[(w16 + grp + 8) * AS + kk + thr];
            uint32_t a2 = Qs[(w16 + grp)     * AS + kk + thr + 4];
            uint32_t a3 = Qs[(w16 + grp + 8) * AS + kk + thr + 4];
            #pragma unroll
            for (int ns = 0; ns < 8; ns++) {
                uint32_t b0 = Ks[(ns * 8 + grp) * AS + kk + thr];
                uint32_t b1 = Ks[(ns * 8 + grp) * AS + kk + thr + 4];
                mma_tf32(sacc[ns][0], sacc[ns][1], sacc[ns][2], sacc[ns][3],
                         a0, a1, a2, a3, b0, b1);
            }
        }

        // Scale + prefix mask + tile max
        float tmax0 = NEGINF, tmax1 = NEGINF;
        #pragma unroll
        for (int ns = 0; ns < 8; ns++) {
            int j0 = t * KT + ns * 8 + thr * 2;
            sacc[ns][0] = (j0     < km0) ? sacc[ns][0] * 0.125f : NEGINF;
            sacc[ns][1] = (j0 + 1 < km0) ? sacc[ns][1] * 0.125f : NEGINF;
            sacc[ns][2] = (j0     < km1) ? sacc[ns][2] * 0.125f : NEGINF;
            sacc[ns][3] = (j0 + 1 < km1) ? sacc[ns][3] * 0.125f : NEGINF;
            tmax0 = fmaxf(tmax0, fmaxf(sacc[ns][0], sacc[ns][1]));
            tmax1 = fmaxf(tmax1, fmaxf(sacc[ns][2], sacc[ns][3]));
        }
        tmax0 = fmaxf(tmax0, __shfl_xor_sync(0xFFFFFFFFu, tmax0, 1));
        tmax0 = fmaxf(tmax0, __shfl_xor_sync(0xFFFFFFFFu, tmax0, 2));
        tmax1 = fmaxf(tmax1, __shfl_xor_sync(0xFFFFFFFFu, tmax1, 1));
        tmax1 = fmaxf(tmax1, __shfl_xor_sync(0xFFFFFFFFu, tmax1, 2));

        float mn0 = fmaxf(m0, tmax0);
        float mn1 = fmaxf(m1, tmax1);
        float cr0 = __expf(m0 - mn0);
        float cr1 = __expf(m1 - mn1);
        m0 = mn0; m1 = mn1;

        float rs0 = 0.f, rs1 = 0.f;
        #pragma unroll
        for (int ns = 0; ns < 8; ns++) {
            sacc[ns][0] = __expf(sacc[ns][0] - mn0);
            sacc[ns][1] = __expf(sacc[ns][1] - mn0);
            sacc[ns][2] = __expf(sacc[ns][2] - mn1);
            sacc[ns][3] = __expf(sacc[ns][3] - mn1);
            rs0 += sacc[ns][0] + sacc[ns][1];
            rs1 += sacc[ns][2] + sacc[ns][3];
        }
        rs0 += __shfl_xor_sync(0xFFFFFFFFu, rs0, 1);
        rs0 += __shfl_xor_sync(0xFFFFFFFFu, rs0, 2);
        rs1 += __shfl_xor_sync(0xFFFFFFFFu, rs1, 1);
        rs1 += __shfl_xor_sync(0xFFFFFFFFu, rs1, 2);
        l0 = l0 * cr0 + rs0;
        l1 = l1 * cr1 + rs1;

        #pragma unroll
        for (int no = 0; no < 8; no++) {
            oacc[no][0] *= cr0; oacc[no][1] *= cr0;
            oacc[no][2] *= cr1; oacc[no][3] *= cr1;
        }

        // P tile (warp-private rows) as tf32
        #pragma unroll
        for (int ns = 0; ns < 8; ns++) {
            int col = ns * 8 + thr * 2;
            Ps[(w16 + grp)     * AS + col]     = to_tf32(sacc[ns][0]);
            Ps[(w16 + grp)     * AS + col + 1] = to_tf32(sacc[ns][1]);
            Ps[(w16 + grp + 8) * AS + col]     = to_tf32(sacc[ns][2]);
            Ps[(w16 + grp + 8) * AS + col + 1] = to_tf32(sacc[ns][3]);
        }
        __syncwarp();

        // O += P V  (B operand from Vs[key][d])
        #pragma unroll
        for (int kk = 0; kk < 64; kk += 8) {
            uint32_t a0 = Ps[(w16 + grp)     * AS + kk + thr];
            uint32_t a1 = Ps[(w16 + grp + 8) * AS + kk + thr];
            uint32_t a2 = Ps[(w16 + grp)     * AS + kk + thr + 4];
            uint32_t a3 = Ps[(w16 + grp + 8) * AS + kk + thr + 4];
            #pragma unroll
            for (int no = 0; no < 8; no++) {
                uint32_t b0 = Vs[(kk + thr)     * AS + no * 8 + grp];
                uint32_t b1 = Vs[(kk + thr + 4) * AS + no * 8 + grp];
                mma_tf32(oacc[no][0], oacc[no][1], oacc[no][2], oacc[no][3],
                         a0, a1, a2, a3, b0, b1);
            }
        }
    }

    // Normalize, write directly into tiled tf32 buffer g_aot.
    float inv0 = 1.f / l0;
    float inv1 = 1.f / l1;
    #pragma unroll
    for (int no = 0; no < 8; no++) {
        int d = no * 8 + thr * 2;
        int e = h * HD + d;
        int ktile = e >> 5;
        int c = e & 31;
        uint32_t coff = (uint32_t)((c & 3) * 8 + (c >> 2));
        if (gr0 < SEQ) {
            int mg = b * SEQ + gr0;
            uint32_t* p = g_aot + ((size_t)((mg >> 7) * KTILES + ktile) * 128 + (mg & 127)) * 32 + coff;
            p[0] = to_tf32(oacc[no][0] * inv0);
            p[8] = to_tf32(oacc[no][1] * inv0);
        }
        if (gr1 < SEQ) {
            int mg = b * SEQ + gr1;
            uint32_t* p = g_aot + ((size_t)((mg >> 7) * KTILES + ktile) * 128 + (mg & 127)) * 32 + coff;
            p[0] = to_tf32(oacc[no][2] * inv1);
            p[8] = to_tf32(oacc[no][3] * inv1);
        }
    }
}

// ---------------------------------------------------------------------------

extern "C" void kernel_launch(void* const* d_in, const int* in_sizes, int n_in,
                              void* d_out, int out_size) {
    const float* x      = (const float*)d_in[0];
    const float* qkv_w  = (const float*)d_in[1];
    const float* qkv_b  = (const float*)d_in[2];
    const float* proj_w = (const float*)d_in[3];
    const float* proj_b = (const float*)d_in[4];
    float* out = (float*)d_out;

    uint32_t* xt;  cudaGetSymbolAddress((void**)&xt,  g_xt);
    uint32_t* aot; cudaGetSymbolAddress((void**)&aot, g_aot);
    uint32_t* wq;  cudaGetSymbolAddress((void**)&wq,  g_wq);
    uint32_t* wp;  cudaGetSymbolAddress((void**)&wp,  g_wp);

    const int smem_gemm = 2 * 2 * 4096 * (int)sizeof(uint32_t);  // 65536
    const int smem_attn = (128 * AS + KT * AS + KT * AS + 128 * AS) * (int)sizeof(uint32_t);
    cudaFuncSetAttribute(gemm_fmt_kernel, cudaFuncAttributeMaxDynamicSharedMemorySize, smem_gemm);
    cudaFuncSetAttribute(attn_mma_kernel, cudaFuncAttributeMaxDynamicSharedMemorySize, smem_attn);

    // Format passes
    fmt_kernel<<<MROWS, 192>>>(x, xt);
    fmt_kernel<<<QKV_COLS, 192>>>(qkv_w, wq);
    fmt_kernel<<<DIM, 192>>>(proj_w, wp);

    // QKV GEMM (R12 geometry)
    dim3 gQkv(QKV_COLS / 128, ROWTILES);   // 18 x 171
    gemm_fmt_kernel<<<gQkv, 256, smem_gemm>>>(xt, wq, qkv_b, nullptr, 0);

    // Attention (writes g_aot tiled)
    dim3 gAttn(BQ * NH, 3);                // 768 x 3
    attn_mma_kernel<<<gAttn, 256, smem_attn>>>();

    // Proj GEMM
    dim3 gProj(DIM / 128, ROWTILES);       // 6 x 171
    gemm_fmt_kernel<<<gProj, 256, smem_gemm>>>(aot, wp, proj_b, out, 1);
}

// round 16
// speedup vs baseline: 1.3144x; 1.0881x over previous
#include <cuda_runtime.h>
#include <cuda_bf16.h>
#include <cstdint>

#define BQ   64
#define SEQ  341
#define DIM  768
#define NH   12
#define HD   64
#define MROWS (BQ * SEQ)      // 21824
#define QKV_COLS (3 * DIM)    // 2304
#define ROWTILES 171          // ceil(21824/128)
#define KTILES   24           // 768/32
#define PADROWS  64           // zero padding rows for OOB tile reads

// Scratch (no device allocation allowed). __device__ globals are zero-init;
// padding rows are never written so they stay zero across graph replays.
// q/k/v hold tf32 BIT PATTERNS (written pre-converted by the qkv epilogue).
__device__ uint32_t g_q[((size_t)BQ * NH * SEQ + PADROWS) * HD];
__device__ uint32_t g_k[((size_t)BQ * NH * SEQ + PADROWS) * HD];
__device__ uint32_t g_v[((size_t)BQ * NH * SEQ + PADROWS) * HD];

// Pre-formatted tf32-bit tiled buffers: [tile][kTile][r=128][permuted c=32]
__device__ uint32_t g_xt[(size_t)ROWTILES * KTILES * 4096];
__device__ uint32_t g_aot[(size_t)ROWTILES * KTILES * 4096];
__device__ uint32_t g_wq[(size_t)(QKV_COLS / 128) * KTILES * 4096];
__device__ uint32_t g_wp[(size_t)(DIM / 128) * KTILES * 4096];

// ---------------------------------------------------------------------------
// Helpers
// ---------------------------------------------------------------------------

__device__ __forceinline__ uint32_t to_tf32(float x) {
    uint32_t y;
    asm("cvt.rna.tf32.f32 %0, %1;" : "=r"(y) : "f"(x));
    return y;
}

__device__ __forceinline__ void mma_tf32(float& c0, float& c1, float& c2, float& c3,
                                         uint32_t a0, uint32_t a1, uint32_t a2, uint32_t a3,
                                         uint32_t b0, uint32_t b1) {
    asm volatile(
        "mma.sync.aligned.m16n8k8.row.col.f32.tf32.tf32.f32 "
        "{%0,%1,%2,%3}, {%4,%5,%6,%7}, {%8,%9}, {%0,%1,%2,%3};\n"
        : "+f"(c0), "+f"(c1), "+f"(c2), "+f"(c3)
        : "r"(a0), "r"(a1), "r"(a2), "r"(a3), "r"(b0), "r"(b1));
}

#define CP_ASYNC16(dst32, src) \
    asm volatile("cp.async.cg.shared.global [%0], [%1], 16;\n" :: "r"(dst32), "l"(src))
#define CP_COMMIT()  asm volatile("cp.async.commit_group;\n" ::: "memory")
#define CP_WAIT0()   asm volatile("cp.async.wait_group 0;\n" ::: "memory")

// ---------------------------------------------------------------------------
// Format pass: fp32 row-major [nrows x 768] -> tiled permuted tf32 bits.
// word(tile,kt,r,c) = ((tile*24+kt)*128 + r)*32 + (c&3)*8 + (c>>2)
// ---------------------------------------------------------------------------

__global__ __launch_bounds__(192) void fmt_kernel(
    const float* __restrict__ src, uint32_t* __restrict__ dst)
{
    const int m = blockIdx.x;
    const int f = threadIdx.x;          // float4 index 0..191
    const float4 v = *reinterpret_cast<const float4*>(src + (size_t)m * DIM + f * 4);
    const int rowTile = m >> 7;
    const int r = m & 127;
    const int kt = f >> 3;
    const int f4 = f & 7;
    uint32_t* p = dst + ((size_t)(rowTile * KTILES + kt) * 128 + r) * 32 + f4;
    p[0]  = to_tf32(v.x);
    p[8]  = to_tf32(v.y);
    p[16] = to_tf32(v.z);
    p[24] = to_tf32(v.w);
}

// ---------------------------------------------------------------------------
// TF32 GEMM on pre-formatted tiles (128x128, BK=32, 8 warps 4x2, cp.async
// double-buffered). Smem tiles XOR-swizzled at 4-word granularity:
//   word(r, c) -> r*32 + (c ^ ((r & 1) * 4))
// so the two row-parities in each 8-lane LDS.128 phase hit disjoint bank
// groups (kills the 2-way conflict of the plain stride-32 layout).
// mode 0: scatter tf32 bits to g_q/g_k/g_v. mode 1: out[m][e] = val.
// ---------------------------------------------------------------------------

__global__ __launch_bounds__(256) void gemm_fmt_kernel(
    const uint32_t* __restrict__ At, const uint32_t* __restrict__ Wt,
    const float* __restrict__ bias, float* __restrict__ out, int mode)
{
    extern __shared__ uint32_t sh[];
    uint32_t* sA = sh;           // [2][4096]
    uint32_t* sB = sh + 8192;    // [2][4096]

    const int tid  = threadIdx.x;
    const int warp = tid >> 5;
    const int lane = tid & 31;
    const int warp_m = warp >> 1;
    const int warp_n = warp & 1;
    const int grp  = lane >> 2;
    const int thr  = lane & 3;
    const int colT = blockIdx.x;
    const int rowT = blockIdx.y;

    const uint32_t* gA = At + (size_t)rowT * KTILES * 4096;
    const uint32_t* gB = Wt + (size_t)colT * KTILES * 4096;

    float acc[2][8][4];
    #pragma unroll
    for (int i = 0; i < 2; i++)
        #pragma unroll
        for (int j = 0; j < 8; j++)
            #pragma unroll
            for (int c = 0; c < 4; c++) acc[i][j][c] = 0.f;

    // Swizzled smem word offset for a linear tile word offset (4-aligned).
    // r = off>>5, c = off&31 -> r*32 + (c ^ ((r&1)*4))
    #define SWZ(off) (((off) & ~31) | (((off) & 31) ^ ((((off) >> 5) & 1) << 2)))

    {
        uint32_t dA = (uint32_t)__cvta_generic_to_shared(sA);
        uint32_t dB = (uint32_t)__cvta_generic_to_shared(sB);
        #pragma unroll
        for (int i = 0; i < 4; i++) {
            int off = (i * 256 + tid) * 4;
            int sw  = SWZ(off);
            CP_ASYNC16(dA + sw * 4, gA + off);
            CP_ASYNC16(dB + sw * 4, gB + off);
        }
        CP_COMMIT();
    }

    const int sw4 = (grp & 1) << 2;   // fragment-load column XOR (row parity = grp parity)

    for (int kt = 0; kt < KTILES; kt++) {
        const int cur = kt & 1;
        CP_WAIT0();
        __syncthreads();

        if (kt + 1 < KTILES) {
            const int nxt = cur ^ 1;
            uint32_t dA = (uint32_t)__cvta_generic_to_shared(sA + nxt * 4096);
            uint32_t dB = (uint32_t)__cvta_generic_to_shared(sB + nxt * 4096);
            const uint32_t* srcA = gA + (size_t)(kt + 1) * 4096;
            const uint32_t* srcB = gB + (size_t)(kt + 1) * 4096;
            #pragma unroll
            for (int i = 0; i < 4; i++) {
                int off = (i * 256 + tid) * 4;
                int sw  = SWZ(off);
                CP_ASYNC16(dA + sw * 4, srcA + off);
                CP_ASYNC16(dB + sw * 4, srcB + off);
            }
            CP_COMMIT();
        }

        const uint32_t* A0 = sA + cur * 4096;
        const uint32_t* B0 = sB + cur * 4096;

        #pragma unroll
        for (int half = 0; half < 2; half++) {
            const int fc = (thr * 8 + half * 4) ^ sw4;   // swizzled fragment column
            uint4 va[2][2];
            #pragma unroll
            for (int ms = 0; ms < 2; ms++) {
                int r0 = warp_m * 32 + ms * 16 + grp;
                va[ms][0] = *reinterpret_cast<const uint4*>(&A0[r0 * 32 + fc]);
                va[ms][1] = *reinterpret_cast<const uint4*>(&A0[(r0 + 8) * 32 + fc]);
            }
            #pragma unroll
            for (int ns = 0; ns < 8; ns++) {
                int rn = warp_n * 64 + ns * 8 + grp;
                uint4 vb = *reinterpret_cast<const uint4*>(&B0[rn * 32 + fc]);
                #pragma unroll
                for (int ms = 0; ms < 2; ms++) {
                    mma_tf32(acc[ms][ns][0], acc[ms][ns][1], acc[ms][ns][2], acc[ms][ns][3],
                             va[ms][0].x, va[ms][1].x, va[ms][0].y, va[ms][1].y,
                             vb.x, vb.y);
                    mma_tf32(acc[ms][ns][0], acc[ms][ns][1], acc[ms][ns][2], acc[ms][ns][3],
                             va[ms][0].z, va[ms][1].z, va[ms][0].w, va[ms][1].w,
                             vb.z, vb.w);
                }
            }
        }
        __syncthreads();
    }

    // Epilogue
    #pragma unroll
    for (int ms = 0; ms < 2; ms++) {
        #pragma unroll
        for (int ns = 0; ns < 8; ns++) {
            #pragma unroll
            for (int c = 0; c < 4; c++) {
                int m = rowT * 128 + warp_m * 32 + ms * 16 + grp + ((c >= 2) ? 8 : 0);
                if (m >= MROWS) continue;
                int e = colT * 128 + warp_n * 64 + ns * 8 + thr * 2 + (c & 1);
                float val = acc[ms][ns][c] + __ldg(&bias[e]);
                if (mode == 0) {
                    int b = m / SEQ;
                    int n = m - b * SEQ;
                    int which = e / DIM;
                    int d = e - which * DIM;
                    int h = d >> 6;
                    int hh = d & 63;
                    uint32_t* dst = (which == 0) ? g_q : (which == 1) ? g_k : g_v;
                    dst[(((size_t)b * NH + h) * SEQ + n) * HD + hh] = to_tf32(val);
                } else {
                    out[(size_t)m * DIM + e] = val;
                }
            }
        }
    }
    #undef SWZ
}

// ---------------------------------------------------------------------------
// Tensor-core flash attention, K-tile 64, cp.async staging of pre-converted
// tf32 bits. 104 KB smem -> 2 CTAs/SM. (Validated R14 version.)
// ---------------------------------------------------------------------------

#define AS 68    // row stride (64 + 4)
#define KT 64    // key tile
#define NEGINF (-1e30f)

__device__ __forceinline__ int kmax_for_row(int r) {
    if (r == 0)  return SEQ;   // CLS attends everywhere
    if (r < 5)   return 5;
    if (r < 21)  return 21;
    if (r < 85)  return 85;
    return SEQ;
}

__global__ __launch_bounds__(256) void attn_mma_kernel() {
    extern __shared__ uint32_t sm[];
    uint32_t* Qs = sm;                 // [128][AS]
    uint32_t* Ks = Qs + 128 * AS;      // [64][AS]
    uint32_t* Vs = Ks + KT * AS;       // [64][AS]
    uint32_t* Ps = Vs + KT * AS;       // [128][AS]

    const int tid  = threadIdx.x;
    const int warp = tid >> 5;
    const int lane = tid & 31;
    const int grp  = lane >> 2;
    const int thr  = lane & 3;
    const int bh   = blockIdx.x;
    const int qt   = blockIdx.y;
    const size_t base = (size_t)bh * SEQ * HD;
    const int b = bh / NH;
    const int h = bh - b * NH;
    const int w16 = warp * 16;

    const uint32_t qsA = (uint32_t)__cvta_generic_to_shared(Qs);
    const uint32_t ksA = (uint32_t)__cvta_generic_to_shared(Ks);
    const uint32_t vsA = (uint32_t)__cvta_generic_to_shared(Vs);

    // Stage Q tile [128 x 64] via cp.async (tf32 bits; padded rows read zeros)
    #pragma unroll
    for (int i = 0; i < 8; i++) {
        int idx = i * 256 + tid;        // 0..2047
        int r   = idx >> 4;             // 0..127
        int c4  = (idx & 15) * 4;
        CP_ASYNC16(qsA + (r * AS + c4) * 4,
                   g_q + base + (size_t)(qt * 128 + r) * HD + c4);
    }
    CP_COMMIT();

    const int gr0 = qt * 128 + w16 + grp;
    const int gr1 = gr0 + 8;
    const int km0 = kmax_for_row(gr0);
    const int km1 = kmax_for_row(gr1);
    const int wkm = (qt == 0 && warp == 0) ? SEQ : kmax_for_row(qt * 128 + w16 + 15);

    float m0 = NEGINF, m1 = NEGINF, l0 = 0.f, l1 = 0.f;
    float oacc[8][4];
    #pragma unroll
    for (int no = 0; no < 8; no++)
        #pragma unroll
        for (int c = 0; c < 4; c++) oacc[no][c] = 0.f;

    for (int t = 0; t < 6; t++) {
        __syncthreads();   // prior tile's smem reads done

        // Stage K and V tiles [64 x 64] via cp.async
        #pragma unroll
        for (int i = 0; i < 4; i++) {
            int idx = i * 256 + tid;    // 0..1023
            int r   = idx >> 4;         // 0..63
            int c4  = (idx & 15) * 4;
            size_t goff = base + (size_t)(t * KT + r) * HD + c4;
            CP_ASYNC16(ksA + (r * AS + c4) * 4, g_k + goff);
            CP_ASYNC16(vsA + (r * AS + c4) * 4, g_v + goff);
        }
        CP_COMMIT();
        CP_WAIT0();        // Q (t=0) + this tile's K/V complete
        __syncthreads();

        if (t * KT >= wkm) continue;

        // S = Q K^T : 16 q-rows x 64 keys
        float sacc[8][4];
        #pragma unroll
        for (int ns = 0; ns < 8; ns++)
            #pragma unroll
            for (int c = 0; c < 4; c++) sacc[ns][c] = 0.f;

        #pragma unroll
        for (int kk = 0; kk < 64; kk += 8) {
            uint32_t a0 = Qs[(w16 + grp)     * AS + kk + thr];
            uint32_t a1 = Qs[(w16 + grp + 8) * AS + kk + thr];
            uint32_t a2 = Qs[(w16 + grp)     * AS + kk + thr + 4];
            uint32_t a3 = Qs[(w16 + grp + 8) * AS + kk + thr + 4];
            #pragma unroll
            for (int ns = 0; ns < 8; ns++) {
                uint32_t b0 = Ks[(ns * 8 + grp) * AS + kk + thr];
                uint32_t b1 = Ks[(ns * 8 + grp) * AS + kk + thr + 4];
                mma_tf32(sacc[ns][0], sacc[ns][1], sacc[ns][2], sacc[ns][3],
                         a0, a1, a2, a3, b0, b1);
            }
        }

        // Scale + prefix mask + tile max
        float tmax0 = NEGINF, tmax1 = NEGINF;
        #pragma unroll
        for (int ns = 0; ns < 8; ns++) {
            int j0 = t * KT + ns * 8 + thr * 2;
            sacc[ns][0] = (j0     < km0) ? sacc[ns][0] * 0.125f : NEGINF;
            sacc[ns][1] = (j0 + 1 < km0) ? sacc[ns][1] * 0.125f : NEGINF;
            sacc[ns][2] = (j0     < km1) ? sacc[ns][2] * 0.125f : NEGINF;
            sacc[ns][3] = (j0 + 1 < km1) ? sacc[ns][3] * 0.125f : NEGINF;
            tmax0 = fmaxf(tmax0, fmaxf(sacc[ns][0], sacc[ns][1]));
            tmax1 = fmaxf(tmax1, fmaxf(sacc[ns][2], sacc[ns][3]));
        }
        tmax0 = fmaxf(tmax0, __shfl_xor_sync(0xFFFFFFFFu, tmax0, 1));
        tmax0 = fmaxf(tmax0, __shfl_xor_sync(0xFFFFFFFFu, tmax0, 2));
        tmax1 = fmaxf(tmax1, __shfl_xor_sync(0xFFFFFFFFu, tmax1, 1));
        tmax1 = fmaxf(tmax1, __shfl_xor_sync(0xFFFFFFFFu, tmax1, 2));

        float mn0 = fmaxf(m0, tmax0);
        float mn1 = fmaxf(m1, tmax1);
        float cr0 = __expf(m0 - mn0);
        float cr1 = __expf(m1 - mn1);
        m0 = mn0; m1 = mn1;

        float rs0 = 0.f, rs1 = 0.f;
        #pragma unroll
        for (int ns = 0; ns < 8; ns++) {
            sacc[ns][0] = __expf(sacc[ns][0] - mn0);
            sacc[ns][1] = __expf(sacc[ns][1] - mn0);
            sacc[ns][2] = __expf(sacc[ns][2] - mn1);
            sacc[ns][3] = __expf(sacc[ns][3] - mn1);
            rs0 += sacc[ns][0] + sacc[ns][1];
            rs1 += sacc[ns][2] + sacc[ns][3];
        }
        rs0 += __shfl_xor_sync(0xFFFFFFFFu, rs0, 1);
        rs0 += __shfl_xor_sync(0xFFFFFFFFu, rs0, 2);
        rs1 += __shfl_xor_sync(0xFFFFFFFFu, rs1, 1);
        rs1 += __shfl_xor_sync(0xFFFFFFFFu, rs1, 2);
        l0 = l0 * cr0 + rs0;
        l1 = l1 * cr1 + rs1;

        #pragma unroll
        for (int no = 0; no < 8; no++) {
            oacc[no][0] *= cr0; oacc[no][1] *= cr0;
            oacc[no][2] *= cr1; oacc[no][3] *= cr1;
        }

        // P tile (warp-private rows) as tf32
        #pragma unroll
        for (int ns = 0; ns < 8; ns++) {
            int col = ns * 8 + thr * 2;
            Ps[(w16 + grp)     * AS + col]     = to_tf32(sacc[ns][0]);
            Ps[(w16 + grp)     * AS + col + 1] = to_tf32(sacc[ns][1]);
            Ps[(w16 + grp + 8) * AS + col]     = to_tf32(sacc[ns][2]);
            Ps[(w16 + grp + 8) * AS + col + 1] = to_tf32(sacc[ns][3]);
        }
        __syncwarp();

        // O += P V  (B operand from Vs[key][d])
        #pragma unroll
        for (int kk = 0; kk < 64; kk += 8) {
            uint32_t a0 = Ps[(w16 + grp)     * AS + kk + thr];
            uint32_t a1 = Ps[(w16 + grp + 8) * AS + kk + thr];
            uint32_t a2 = Ps[(w16 + grp)     * AS + kk + thr + 4];
            uint32_t a3 = Ps[(w16 + grp + 8) * AS + kk + thr + 4];
            #pragma unroll
            for (int no = 0; no < 8; no++) {
                uint32_t b0 = Vs[(kk + thr)     * AS + no * 8 + grp];
                uint32_t b1 = Vs[(kk + thr + 4) * AS + no * 8 + grp];
                mma_tf32(oacc[no][0], oacc[no][1], oacc[no][2], oacc[no][3],
                         a0, a1, a2, a3, b0, b1);
            }
        }
    }

    // Normalize, write directly into tiled tf32 buffer g_aot.
    float inv0 = 1.f / l0;
    float inv1 = 1.f / l1;
    #pragma unroll
    for (int no = 0; no < 8; no++) {
        int d = no * 8 + thr * 2;
        int e = h * HD + d;
        int ktile = e >> 5;
        int c = e & 31;
        uint32_t coff = (uint32_t)((c & 3) * 8 + (c >> 2));
        if (gr0 < SEQ) {
            int mg = b * SEQ + gr0;
            uint32_t* p = g_aot + ((size_t)((mg >> 7) * KTILES + ktile) * 128 + (mg & 127)) * 32 + coff;
            p[0] = to_tf32(oacc[no][0] * inv0);
            p[8] = to_tf32(oacc[no][1] * inv0);
        }
        if (gr1 < SEQ) {
            int mg = b * SEQ + gr1;
            uint32_t* p = g_aot + ((size_t)((mg >> 7) * KTILES + ktile) * 128 + (mg & 127)) * 32 + coff;
            p[0] = to_tf32(oacc[no][2] * inv1);
            p[8] = to_tf32(oacc[no][3] * inv1);
        }
    }
}

// ---------------------------------------------------------------------------

extern "C" void kernel_launch(void* const* d_in, const int* in_sizes, int n_in,
                              void* d_out, int out_size) {
    const float* x      = (const float*)d_in[0];
    const float* qkv_w  = (const float*)d_in[1];
    const float* qkv_b  = (const float*)d_in[2];
    const float* proj_w = (const float*)d_in[3];
    const float* proj_b = (const float*)d_in[4];
    float* out = (float*)d_out;

    uint32_t* xt;  cudaGetSymbolAddress((void**)&xt,  g_xt);
    uint32_t* aot; cudaGetSymbolAddress((void**)&aot, g_aot);
    uint32_t* wq;  cudaGetSymbolAddress((void**)&wq,  g_wq);
    uint32_t* wp;  cudaGetSymbolAddress((void**)&wp,  g_wp);

    const int smem_gemm = 2 * 2 * 4096 * (int)sizeof(uint32_t);  // 65536
    const int smem_attn = (128 * AS + KT * AS + KT * AS + 128 * AS) * (int)sizeof(uint32_t);
    cudaFuncSetAttribute(gemm_fmt_kernel, cudaFuncAttributeMaxDynamicSharedMemorySize, smem_gemm);
    cudaFuncSetAttribute(attn_mma_kernel, cudaFuncAttributeMaxDynamicSharedMemorySize, smem_attn);

    // Format passes
    fmt_kernel<<<MROWS, 192>>>(x, xt);
    fmt_kernel<<<QKV_COLS, 192>>>(qkv_w, wq);
    fmt_kernel<<<DIM, 192>>>(proj_w, wp);

    // QKV GEMM
    dim3 gQkv(QKV_COLS / 128, ROWTILES);   // 18 x 171
    gemm_fmt_kernel<<<gQkv, 256, smem_gemm>>>(xt, wq, qkv_b, nullptr, 0);

    // Attention (writes g_aot tiled)
    dim3 gAttn(BQ * NH, 3);                // 768 x 3
    attn_mma_kernel<<<gAttn, 256, smem_attn>>>();

    // Proj GEMM
    dim3 gProj(DIM / 128, ROWTILES);       // 6 x 171
    gemm_fmt_kernel<<<gProj, 256, smem_gemm>>>(aot, wp, proj_b, out, 1);
}